// round 15
// baseline (speedup 1.0000x reference)
#include <cuda_runtime.h>
#include <cuda_fp16.h>
#include <cstdint>

#define T_ROWS 16384
#define D_IN   1024
#define D_MID  4096
#define D_OUT  1024

// GEMM tiling: 128x128 CTA tile, 8 warps (2Mx4N) of 64x32, 2 CTAs/SM
#define BM 128
#define BN 128
#define BK 64
#define ROWB 128                   // bytes per smem row (64 halves), XOR-swizzled
#define A_ST (BM * ROWB)           // 16384 B
#define B_ST (BN * ROWB)           // 16384 B
#define STG_BYTES (A_ST + B_ST)    // 32768 B
#define DYN_SMEM (3 * STG_BYTES + 128)   // 98432 B -> 2 CTAs per SM

// -------- scratch (static device globals; no allocs allowed) --------
__device__ __half g_XS[(size_t)T_ROWS * D_IN];    // x * up_signs, fp16
__device__ __half g_W1[(size_t)D_MID * D_IN];     // up_wq * H (blockwise), fp16
__device__ __half g_W2[(size_t)D_OUT * D_MID];    // (down_wq * H) * diag(down_signs), fp16
__device__ __half g_AR[(size_t)T_ROWS * D_MID];   // gelu(h * up_scale), fp16

// ---------------- helpers ----------------
static __device__ __forceinline__ uint32_t s2u(const void* p) {
    return (uint32_t)__cvta_generic_to_shared(p);
}
static __device__ __forceinline__ void cp16(uint32_t dst, const void* src) {
    asm volatile("cp.async.cg.shared.global [%0], [%1], 16;" :: "r"(dst), "l"(src));
}
static __device__ __forceinline__ void cp_commit() { asm volatile("cp.async.commit_group;" ::: "memory"); }
template <int N>
static __device__ __forceinline__ void cp_wait() { asm volatile("cp.async.wait_group %0;" :: "n"(N) : "memory"); }

static __device__ __forceinline__ void ldsm_x4(uint32_t& r0, uint32_t& r1, uint32_t& r2, uint32_t& r3,
                                               uint32_t addr) {
    asm volatile("ldmatrix.sync.aligned.m8n8.x4.shared.b16 {%0,%1,%2,%3}, [%4];"
                 : "=r"(r0), "=r"(r1), "=r"(r2), "=r"(r3) : "r"(addr));
}
static __device__ __forceinline__ void mma16816(float* c, const uint32_t* a, const uint32_t* b) {
    asm volatile(
        "mma.sync.aligned.m16n8k16.row.col.f32.f16.f16.f32 "
        "{%0,%1,%2,%3}, {%4,%5,%6,%7}, {%8,%9}, {%0,%1,%2,%3};"
        : "+f"(c[0]), "+f"(c[1]), "+f"(c[2]), "+f"(c[3])
        : "r"(a[0]), "r"(a[1]), "r"(a[2]), "r"(a[3]), "r"(b[0]), "r"(b[1]));
}
static __device__ __forceinline__ float gelu_f(float v) {
    float t = 1.5957691216057308f * (v + 0.044715f * v * v * v);
    return v * (1.0f / (1.0f + __expf(-t)));
}

// ================= merged prep =================
#define XS_BLK (T_ROWS * D_IN / 4 / 256)           // 16384
#define W1_BLK ((D_MID * D_IN / 128) / 8)          // 4096
#define W2_BLK ((D_OUT * D_MID / 128) / 8)         // 4096
__global__ void prep_kernel(const float* __restrict__ x, const float* __restrict__ up_signs,
                            __half* __restrict__ XS,
                            const float* __restrict__ w1, __half* __restrict__ W1,
                            const float* __restrict__ w2, const float* __restrict__ down_signs,
                            __half* __restrict__ W2) {
    int b = blockIdx.x;
    if (b < XS_BLK) {
        int i = b * 256 + threadIdx.x;
        float4 v = reinterpret_cast<const float4*>(x)[i];
        int col = (i * 4) & (D_IN - 1);
        float4 s = *reinterpret_cast<const float4*>(up_signs + col);
        reinterpret_cast<__half2*>(XS)[2 * i]     = __floats2half2_rn(v.x * s.x, v.y * s.y);
        reinterpret_cast<__half2*>(XS)[2 * i + 1] = __floats2half2_rn(v.z * s.z, v.w * s.w);
        return;
    }
    const float* w;  __half* out;  const float* signs;  int rowlen;
    if (b < XS_BLK + W1_BLK) { b -= XS_BLK;          w = w1; out = W1; signs = nullptr;     rowlen = D_IN;  }
    else                     { b -= XS_BLK + W1_BLK; w = w2; out = W2; signs = down_signs;  rowlen = D_MID; }
    int warp = b * 8 + (threadIdx.x >> 5);
    int lane = threadIdx.x & 31;
    size_t base = (size_t)warp * 128;
    int colbase = (int)(base % (size_t)rowlen);
    float v[4];
#pragma unroll
    for (int j = 0; j < 4; j++) v[j] = w[base + lane + 32 * j];
#pragma unroll
    for (int len = 1; len <= 16; len <<= 1) {
#pragma unroll
        for (int j = 0; j < 4; j++) {
            float o = __shfl_xor_sync(0xffffffffu, v[j], len);
            v[j] = (lane & len) ? (o - v[j]) : (v[j] + o);
        }
    }
    float t0 = v[0] + v[1], t1 = v[0] - v[1], t2 = v[2] + v[3], t3 = v[2] - v[3];
    v[0] = t0 + t2; v[2] = t0 - t2; v[1] = t1 + t3; v[3] = t1 - t3;
    const float nrm = 0.08838834764831845f;
    if (signs) {
#pragma unroll
        for (int j = 0; j < 4; j++)
            out[base + lane + 32 * j] = __float2half(v[j] * nrm * signs[colbase + lane + 32 * j]);
    } else {
#pragma unroll
        for (int j = 0; j < 4; j++)
            out[base + lane + 32 * j] = __float2half(v[j] * nrm);
    }
}

// ================= GEMM1: 2-tile chained pipeline =================
// Each CTA does two m-adjacent 128x128 tiles at the same n0 with one
// continuous 32-iteration cp.async pipeline (prologue paid once, B k-stages
// re-read L2-hot for tile 1). out fp16 = gelu(acc*scale[n]).
__global__ __launch_bounds__(256, 2)
void gemm1_mma(const __half* __restrict__ A, const __half* __restrict__ B,
               const float* __restrict__ scale, __half* __restrict__ Out,
               int M, int Nfull, int K) {
    extern __shared__ char dsm_raw[];
    char* sb = (char*)((((uintptr_t)dsm_raw) + 127) & ~(uintptr_t)127);
    const uint32_t sbase = s2u(sb);

    const int tid = threadIdx.x;
    const int wid = tid >> 5;
    const int lane = tid & 31;
    const int wm = (wid >> 2) * 64;
    const int wn = (wid & 3) * 32;
    const int m0 = blockIdx.y * (2 * BM);   // two m-tiles per CTA
    const int n0 = blockIdx.x * BN;
    const int KI = K / BK;                  // 16
    const int G = 2 * KI;                   // 32

    float acc[4][4][4];
#pragma unroll
    for (int i = 0; i < 4; i++)
#pragma unroll
        for (int j = 0; j < 4; j++)
#pragma unroll
            for (int e = 0; e < 4; e++) acc[i][j][e] = 0.0f;

    auto load_g = [&](int g) {
        const int kk = g & (KI - 1);
        const int mt = g >> 4;              // 0 or 1
        const int s = g % 3;
        uint32_t aB = sbase + s * STG_BYTES;
        uint32_t bB = aB + A_ST;
        const __half* Ap = A + (size_t)(m0 + mt * BM) * K + kk * BK;
        const __half* Bp = B + (size_t)n0 * K + kk * BK;
#pragma unroll
        for (int i = 0; i < 4; i++) {
            int idx = tid + i * 256;
            int row = idx >> 3, c = idx & 7;
            cp16(aB + (uint32_t)(row * ROWB + ((c ^ (row & 7)) << 4)),
                 Ap + (size_t)row * K + c * 8);
        }
#pragma unroll
        for (int i = 0; i < 4; i++) {
            int idx = tid + i * 256;
            int row = idx >> 3, c = idx & 7;
            cp16(bB + (uint32_t)(row * ROWB + ((c ^ (row & 7)) << 4)),
                 Bp + (size_t)row * K + c * 8);
        }
    };

    const int rowA = wm + (lane & 15);
    const uint32_t rbA = (uint32_t)(rowA * ROWB);
    const uint32_t swA = (uint32_t)(rowA & 7);
    const uint32_t hiA = (uint32_t)(lane >> 4);
    const int rowB = wn + ((lane >> 4) << 3) + (lane & 7);
    const uint32_t rbB = (uint32_t)(A_ST + rowB * ROWB);
    const uint32_t swB = (uint32_t)(rowB & 7);
    const uint32_t hiB = (uint32_t)((lane & 8) >> 3);

    auto do_slice = [&](uint32_t stg, int ks) {
        uint32_t af[4][4], bf[4][2];
        const uint32_t ca = (uint32_t)(2 * ks) + hiA;
        const uint32_t cb = (uint32_t)(2 * ks) + hiB;
#pragma unroll
        for (int i = 0; i < 4; i++)
            ldsm_x4(af[i][0], af[i][1], af[i][2], af[i][3],
                    stg + rbA + (uint32_t)(i * 16 * ROWB) + ((ca ^ swA) << 4));
#pragma unroll
        for (int p = 0; p < 2; p++)
            ldsm_x4(bf[2 * p][0], bf[2 * p][1], bf[2 * p + 1][0], bf[2 * p + 1][1],
                    stg + rbB + (uint32_t)(p * 16 * ROWB) + ((cb ^ swB) << 4));
#pragma unroll
        for (int i = 0; i < 4; i++)
#pragma unroll
            for (int j = 0; j < 4; j++)
                mma16816(acc[i][j], af[i], bf[j]);
    };

    load_g(0); cp_commit();
    load_g(1); cp_commit();

    for (int g = 0; g < G; g++) {
        cp_wait<1>();
        __syncthreads();
        const uint32_t stg = sbase + (g % 3) * STG_BYTES;
        do_slice(stg, 0);
        if (g + 2 < G) load_g(g + 2);
        cp_commit();
#pragma unroll
        for (int ks = 1; ks < 4; ks++) do_slice(stg, ks);

        if ((g & (KI - 1)) == KI - 1) {     // tile finished
            const int me = m0 + (g >> 4) * BM;
#pragma unroll
            for (int i = 0; i < 4; i++) {
#pragma unroll
                for (int j = 0; j < 4; j++) {
                    int row = me + wm + i * 16 + (lane >> 2);
                    int col = n0 + wn + j * 8 + (lane & 3) * 2;
                    float2 s01 = *(const float2*)(scale + col);
                    float v00 = gelu_f(acc[i][j][0] * s01.x);
                    float v01 = gelu_f(acc[i][j][1] * s01.y);
                    float v10 = gelu_f(acc[i][j][2] * s01.x);
                    float v11 = gelu_f(acc[i][j][3] * s01.y);
                    *(__half2*)(Out + (size_t)row * Nfull + col) = __floats2half2_rn(v00, v01);
                    *(__half2*)(Out + (size_t)(row + 8) * Nfull + col) = __floats2half2_rn(v10, v11);
#pragma unroll
                    for (int e = 0; e < 4; e++) acc[i][j][e] = 0.0f;
                }
            }
        }
    }
    cp_wait<0>();
}

// ================= GEMM2: persistent continuous pipeline =================
// out fp32 = acc*scale[n]; KI = K/BK, NTX = N/BN compile-time.
template <int KI, int NTX>
__global__ __launch_bounds__(256, 2)
void gemm2_mma(const __half* __restrict__ A, const __half* __restrict__ B,
               const float* __restrict__ scale, float* __restrict__ Out,
               int M, int Nfull, int K) {
    extern __shared__ char dsm_raw[];
    char* sb = (char*)((((uintptr_t)dsm_raw) + 127) & ~(uintptr_t)127);
    const uint32_t sbase = s2u(sb);

    const int tid = threadIdx.x;
    const int wid = tid >> 5;
    const int lane = tid & 31;
    const int wm = (wid >> 2) * 64;
    const int wn = (wid & 3) * 32;

    const int ntiles = (M / BM) * NTX;
    const int bx = (int)blockIdx.x, gsz = (int)gridDim.x;
    const int myTiles = (ntiles - bx + gsz - 1) / gsz;
    const int G = myTiles * KI;

    auto load_g = [&](int g) {
        const int lt = g / KI;
        const int kk = g % KI;
        const int tile = bx + lt * gsz;
        const int tm0 = (tile / NTX) * BM;
        const int tn0 = (tile % NTX) * BN;
        const int k0 = kk * BK;
        const int s = g % 3;
        uint32_t aB = sbase + s * STG_BYTES;
        uint32_t bB = aB + A_ST;
        const __half* Ap = A + (size_t)tm0 * K + k0;
        const __half* Bp = B + (size_t)tn0 * K + k0;
#pragma unroll
        for (int i = 0; i < 4; i++) {
            int idx = tid + i * 256;
            int row = idx >> 3, c = idx & 7;
            cp16(aB + (uint32_t)(row * ROWB + ((c ^ (row & 7)) << 4)),
                 Ap + (size_t)row * K + c * 8);
        }
#pragma unroll
        for (int i = 0; i < 4; i++) {
            int idx = tid + i * 256;
            int row = idx >> 3, c = idx & 7;
            cp16(bB + (uint32_t)(row * ROWB + ((c ^ (row & 7)) << 4)),
                 Bp + (size_t)row * K + c * 8);
        }
    };

    const int rowA = wm + (lane & 15);
    const uint32_t rbA = (uint32_t)(rowA * ROWB);
    const uint32_t swA = (uint32_t)(rowA & 7);
    const uint32_t hiA = (uint32_t)(lane >> 4);
    const int rowB = wn + ((lane >> 4) << 3) + (lane & 7);
    const uint32_t rbB = (uint32_t)(A_ST + rowB * ROWB);
    const uint32_t swB = (uint32_t)(rowB & 7);
    const uint32_t hiB = (uint32_t)((lane & 8) >> 3);

    float acc[4][4][4];
#pragma unroll
    for (int i = 0; i < 4; i++)
#pragma unroll
        for (int j = 0; j < 4; j++)
#pragma unroll
            for (int e = 0; e < 4; e++) acc[i][j][e] = 0.0f;

    auto do_slice = [&](uint32_t stg, int ks) {
        uint32_t af[4][4], bf[4][2];
        const uint32_t ca = (uint32_t)(2 * ks) + hiA;
        const uint32_t cb = (uint32_t)(2 * ks) + hiB;
#pragma unroll
        for (int i = 0; i < 4; i++)
            ldsm_x4(af[i][0], af[i][1], af[i][2], af[i][3],
                    stg + rbA + (uint32_t)(i * 16 * ROWB) + ((ca ^ swA) << 4));
#pragma unroll
        for (int p = 0; p < 2; p++)
            ldsm_x4(bf[2 * p][0], bf[2 * p][1], bf[2 * p + 1][0], bf[2 * p + 1][1],
                    stg + rbB + (uint32_t)(p * 16 * ROWB) + ((cb ^ swB) << 4));
#pragma unroll
        for (int i = 0; i < 4; i++)
#pragma unroll
            for (int j = 0; j < 4; j++)
                mma16816(acc[i][j], af[i], bf[j]);
    };

    if (G == 0) return;

    load_g(0); cp_commit();
    if (G > 1) load_g(1);
    cp_commit();

    for (int g = 0; g < G; g++) {
        cp_wait<1>();
        __syncthreads();
        const uint32_t stg = sbase + (g % 3) * STG_BYTES;
        do_slice(stg, 0);
        if (g + 2 < G) load_g(g + 2);
        cp_commit();
#pragma unroll
        for (int ks = 1; ks < 4; ks++) do_slice(stg, ks);

        if (((g + 1) % KI) == 0) {
            const int tile = bx + (g / KI) * gsz;
            const int m0 = (tile / NTX) * BM;
            const int n0 = (tile % NTX) * BN;
#pragma unroll
            for (int i = 0; i < 4; i++) {
#pragma unroll
                for (int j = 0; j < 4; j++) {
                    int row = m0 + wm + i * 16 + (lane >> 2);
                    int col = n0 + wn + j * 8 + (lane & 3) * 2;
                    float2 s01 = *(const float2*)(scale + col);
                    *(float2*)(Out + (size_t)row * Nfull + col) =
                        make_float2(acc[i][j][0] * s01.x, acc[i][j][1] * s01.y);
                    *(float2*)(Out + (size_t)(row + 8) * Nfull + col) =
                        make_float2(acc[i][j][2] * s01.x, acc[i][j][3] * s01.y);
#pragma unroll
                    for (int e = 0; e < 4; e++) acc[i][j][e] = 0.0f;
                }
            }
        }
    }
    cp_wait<0>();
}

// ================= host =================
extern "C" void kernel_launch(void* const* d_in, const int* in_sizes, int n_in,
                              void* d_out, int out_size) {
    const float* x          = (const float*)d_in[0];
    const float* up_wq      = (const float*)d_in[1];
    const float* up_scale   = (const float*)d_in[2];
    const float* down_wq    = (const float*)d_in[3];
    const float* down_scale = (const float*)d_in[4];
    const float* up_signs   = (const float*)d_in[5];
    const float* down_signs = (const float*)d_in[6];

    __half *pXS, *pW1, *pW2, *pAR;
    { void* p; cudaGetSymbolAddress(&p, g_XS); pXS = (__half*)p; }
    { void* p; cudaGetSymbolAddress(&p, g_W1); pW1 = (__half*)p; }
    { void* p; cudaGetSymbolAddress(&p, g_W2); pW2 = (__half*)p; }
    { void* p; cudaGetSymbolAddress(&p, g_AR); pAR = (__half*)p; }

    int sms = 148;
    cudaDeviceGetAttribute(&sms, cudaDevAttrMultiProcessorCount, 0);

    cudaFuncSetAttribute(gemm1_mma, cudaFuncAttributeMaxDynamicSharedMemorySize, DYN_SMEM);
    cudaFuncSetAttribute(gemm2_mma<64, 8>, cudaFuncAttributeMaxDynamicSharedMemorySize, DYN_SMEM);

    // 1) merged prep: XS = x*up_signs ; W1' = W1*H ; W2'' = (W2*H)*diag(down_signs)
    prep_kernel<<<XS_BLK + W1_BLK + W2_BLK, 256>>>(x, up_signs, pXS,
                                                   up_wq, pW1,
                                                   down_wq, down_signs, pW2);

    // 2) GEMM1 (2-tile chained): gelu((XS @ W1'^T) * up_scale) -> AR fp16
    {
        dim3 grid(D_MID / BN, T_ROWS / (2 * BM));  // (32, 64)
        gemm1_mma<<<grid, 256, DYN_SMEM>>>(pXS, pW1, up_scale, pAR,
                                           T_ROWS, D_MID, D_IN);
    }

    // 3) GEMM2 (persistent): (AR @ W2''^T) * down_scale -> fp32 out
    {
        int ntiles = (T_ROWS / BM) * (D_OUT / BN);   // 1024
        int grid = 2 * sms; if (grid > ntiles) grid = ntiles;
        gemm2_mma<64, 8><<<grid, 256, DYN_SMEM>>>(pAR, pW2, down_scale, (float*)d_out,
                                                  T_ROWS, D_OUT, D_MID);
    }
}

// round 16
// speedup vs baseline: 1.0239x; 1.0239x over previous
#include <cuda_runtime.h>
#include <cuda_fp16.h>
#include <cstdint>

#define T_ROWS 16384
#define D_IN   1024
#define D_MID  4096
#define D_OUT  1024

// GEMM tiling: 128x128 CTA tile, 8 warps (2Mx4N) of 64x32, 2 CTAs/SM
#define BM 128
#define BN 128
#define BK 64
#define ROWB 128                   // bytes per smem row (64 halves), XOR-swizzled
#define A_ST (BM * ROWB)           // 16384 B
#define B_ST (BN * ROWB)           // 16384 B
#define STG_BYTES (A_ST + B_ST)    // 32768 B
#define DYN_SMEM (3 * STG_BYTES + 128)   // 98432 B -> 2 CTAs per SM

// -------- scratch (static device globals; no allocs allowed) --------
__device__ __half g_XS[(size_t)T_ROWS * D_IN];    // x * up_signs, fp16
__device__ __half g_W1[(size_t)D_MID * D_IN];     // (up_wq * H) * up_scale[row], fp16
__device__ __half g_W2[(size_t)D_OUT * D_MID];    // (down_wq*H)*diag(down_signs)*down_scale[row], fp16
__device__ __half g_AR[(size_t)T_ROWS * D_MID];   // gelu(h), fp16

// ---------------- helpers ----------------
static __device__ __forceinline__ uint32_t s2u(const void* p) {
    return (uint32_t)__cvta_generic_to_shared(p);
}
static __device__ __forceinline__ void cp16(uint32_t dst, const void* src) {
    asm volatile("cp.async.cg.shared.global [%0], [%1], 16;" :: "r"(dst), "l"(src));
}
static __device__ __forceinline__ void cp_commit() { asm volatile("cp.async.commit_group;" ::: "memory"); }
template <int N>
static __device__ __forceinline__ void cp_wait() { asm volatile("cp.async.wait_group %0;" :: "n"(N) : "memory"); }

static __device__ __forceinline__ void ldsm_x4(uint32_t& r0, uint32_t& r1, uint32_t& r2, uint32_t& r3,
                                               uint32_t addr) {
    asm volatile("ldmatrix.sync.aligned.m8n8.x4.shared.b16 {%0,%1,%2,%3}, [%4];"
                 : "=r"(r0), "=r"(r1), "=r"(r2), "=r"(r3) : "r"(addr));
}
static __device__ __forceinline__ void mma16816(float* c, const uint32_t* a, const uint32_t* b) {
    asm volatile(
        "mma.sync.aligned.m16n8k16.row.col.f32.f16.f16.f32 "
        "{%0,%1,%2,%3}, {%4,%5,%6,%7}, {%8,%9}, {%0,%1,%2,%3};"
        : "+f"(c[0]), "+f"(c[1]), "+f"(c[2]), "+f"(c[3])
        : "r"(a[0]), "r"(a[1]), "r"(a[2]), "r"(a[3]), "r"(b[0]), "r"(b[1]));
}
static __device__ __forceinline__ float gelu_f(float v) {
    float t = 1.5957691216057308f * (v + 0.044715f * v * v * v);
    return v * (1.0f / (1.0f + __expf(-t)));
}

// ================= merged prep =================
// blocks [0, XS_BLK): XS = x * up_signs
// blocks [XS_BLK, +W1_BLK): W1' = (W1*H) * up_scale[row]
// blocks [.., +W2_BLK): W2'' = (W2*H) * diag(down_signs) * down_scale[row]
#define XS_BLK (T_ROWS * D_IN / 4 / 256)           // 16384
#define W1_BLK ((D_MID * D_IN / 128) / 8)          // 4096
#define W2_BLK ((D_OUT * D_MID / 128) / 8)         // 4096
__global__ void prep_kernel(const float* __restrict__ x, const float* __restrict__ up_signs,
                            __half* __restrict__ XS,
                            const float* __restrict__ w1, const float* __restrict__ up_scale,
                            __half* __restrict__ W1,
                            const float* __restrict__ w2, const float* __restrict__ down_signs,
                            const float* __restrict__ down_scale, __half* __restrict__ W2) {
    int b = blockIdx.x;
    if (b < XS_BLK) {
        int i = b * 256 + threadIdx.x;
        float4 v = reinterpret_cast<const float4*>(x)[i];
        int col = (i * 4) & (D_IN - 1);
        float4 s = *reinterpret_cast<const float4*>(up_signs + col);
        reinterpret_cast<__half2*>(XS)[2 * i]     = __floats2half2_rn(v.x * s.x, v.y * s.y);
        reinterpret_cast<__half2*>(XS)[2 * i + 1] = __floats2half2_rn(v.z * s.z, v.w * s.w);
        return;
    }
    const float* w;  __half* out;  const float* signs;  const float* rowscale;  int rowlen;
    if (b < XS_BLK + W1_BLK) { b -= XS_BLK;          w = w1; out = W1; signs = nullptr;    rowscale = up_scale;   rowlen = D_IN;  }
    else                     { b -= XS_BLK + W1_BLK; w = w2; out = W2; signs = down_signs; rowscale = down_scale; rowlen = D_MID; }
    int warp = b * 8 + (threadIdx.x >> 5);
    int lane = threadIdx.x & 31;
    size_t base = (size_t)warp * 128;
    int colbase = (int)(base % (size_t)rowlen);
    int wrow = (int)(base / (size_t)rowlen);       // weight row = output column
    float v[4];
#pragma unroll
    for (int j = 0; j < 4; j++) v[j] = w[base + lane + 32 * j];
#pragma unroll
    for (int len = 1; len <= 16; len <<= 1) {
#pragma unroll
        for (int j = 0; j < 4; j++) {
            float o = __shfl_xor_sync(0xffffffffu, v[j], len);
            v[j] = (lane & len) ? (o - v[j]) : (v[j] + o);
        }
    }
    float t0 = v[0] + v[1], t1 = v[0] - v[1], t2 = v[2] + v[3], t3 = v[2] - v[3];
    v[0] = t0 + t2; v[2] = t0 - t2; v[1] = t1 + t3; v[3] = t1 - t3;
    float nrm = 0.08838834764831845f * rowscale[wrow];   // 1/sqrt(128) * per-row scale
    if (signs) {
#pragma unroll
        for (int j = 0; j < 4; j++)
            out[base + lane + 32 * j] = __float2half(v[j] * nrm * signs[colbase + lane + 32 * j]);
    } else {
#pragma unroll
        for (int j = 0; j < 4; j++)
            out[base + lane + 32 * j] = __float2half(v[j] * nrm);
    }
}

// ================= GEMM1: non-persistent (R14 structure) =================
// out fp16 = gelu(acc)  (scale pre-folded into W1)
__global__ __launch_bounds__(256, 2)
void gemm1_mma(const __half* __restrict__ A, const __half* __restrict__ B,
               __half* __restrict__ Out, int M, int Nfull, int K) {
    extern __shared__ char dsm_raw[];
    char* sb = (char*)((((uintptr_t)dsm_raw) + 127) & ~(uintptr_t)127);
    const uint32_t sbase = s2u(sb);

    const int tid = threadIdx.x;
    const int wid = tid >> 5;
    const int lane = tid & 31;
    const int wm = (wid >> 2) * 64;
    const int wn = (wid & 3) * 32;
    const int m0 = blockIdx.y * BM;
    const int n0 = blockIdx.x * BN;
    const int KI = K / BK;

    float acc[4][4][4];
#pragma unroll
    for (int i = 0; i < 4; i++)
#pragma unroll
        for (int j = 0; j < 4; j++)
#pragma unroll
            for (int e = 0; e < 4; e++) acc[i][j][e] = 0.0f;

    auto load_stage = [&](int s, int kk) {
        const int k0 = kk * BK;
        uint32_t aB = sbase + s * STG_BYTES;
        uint32_t bB = aB + A_ST;
        const __half* Ap = A + (size_t)m0 * K + k0;
        const __half* Bp = B + (size_t)n0 * K + k0;
#pragma unroll
        for (int i = 0; i < 4; i++) {
            int idx = tid + i * 256;
            int row = idx >> 3, c = idx & 7;
            cp16(aB + (uint32_t)(row * ROWB + ((c ^ (row & 7)) << 4)),
                 Ap + (size_t)row * K + c * 8);
        }
#pragma unroll
        for (int i = 0; i < 4; i++) {
            int idx = tid + i * 256;
            int row = idx >> 3, c = idx & 7;
            cp16(bB + (uint32_t)(row * ROWB + ((c ^ (row & 7)) << 4)),
                 Bp + (size_t)row * K + c * 8);
        }
    };

    const int rowA = wm + (lane & 15);
    const uint32_t rbA = (uint32_t)(rowA * ROWB);
    const uint32_t swA = (uint32_t)(rowA & 7);
    const uint32_t hiA = (uint32_t)(lane >> 4);
    const int rowB = wn + ((lane >> 4) << 3) + (lane & 7);
    const uint32_t rbB = (uint32_t)(A_ST + rowB * ROWB);
    const uint32_t swB = (uint32_t)(rowB & 7);
    const uint32_t hiB = (uint32_t)((lane & 8) >> 3);

    auto do_slice = [&](uint32_t stg, int ks) {
        uint32_t af[4][4], bf[4][2];
        const uint32_t ca = (uint32_t)(2 * ks) + hiA;
        const uint32_t cb = (uint32_t)(2 * ks) + hiB;
#pragma unroll
        for (int i = 0; i < 4; i++)
            ldsm_x4(af[i][0], af[i][1], af[i][2], af[i][3],
                    stg + rbA + (uint32_t)(i * 16 * ROWB) + ((ca ^ swA) << 4));
#pragma unroll
        for (int p = 0; p < 2; p++)
            ldsm_x4(bf[2 * p][0], bf[2 * p][1], bf[2 * p + 1][0], bf[2 * p + 1][1],
                    stg + rbB + (uint32_t)(p * 16 * ROWB) + ((cb ^ swB) << 4));
#pragma unroll
        for (int i = 0; i < 4; i++)
#pragma unroll
            for (int j = 0; j < 4; j++)
                mma16816(acc[i][j], af[i], bf[j]);
    };

    load_stage(0, 0); cp_commit();
    if (KI > 1) load_stage(1, 1);
    cp_commit();

    for (int k = 0; k < KI; k++) {
        cp_wait<1>();
        __syncthreads();
        const uint32_t stg = sbase + (k % 3) * STG_BYTES;
        do_slice(stg, 0);
        if (k + 2 < KI) load_stage((k + 2) % 3, k + 2);
        cp_commit();
#pragma unroll
        for (int ks = 1; ks < 4; ks++) do_slice(stg, ks);
    }
    cp_wait<0>();

#pragma unroll
    for (int i = 0; i < 4; i++) {
#pragma unroll
        for (int j = 0; j < 4; j++) {
            int row = m0 + wm + i * 16 + (lane >> 2);
            int col = n0 + wn + j * 8 + (lane & 3) * 2;
            float v00 = gelu_f(acc[i][j][0]);
            float v01 = gelu_f(acc[i][j][1]);
            float v10 = gelu_f(acc[i][j][2]);
            float v11 = gelu_f(acc[i][j][3]);
            *(__half2*)(Out + (size_t)row * Nfull + col) = __floats2half2_rn(v00, v01);
            *(__half2*)(Out + (size_t)(row + 8) * Nfull + col) = __floats2half2_rn(v10, v11);
        }
    }
}

// ================= GEMM2: persistent continuous pipeline (R14 structure) =================
// out fp32 = acc  (scale/signs pre-folded into W2); KI = K/BK, NTX = N/BN compile-time.
template <int KI, int NTX>
__global__ __launch_bounds__(256, 2)
void gemm2_mma(const __half* __restrict__ A, const __half* __restrict__ B,
               float* __restrict__ Out, int M, int Nfull, int K) {
    extern __shared__ char dsm_raw[];
    char* sb = (char*)((((uintptr_t)dsm_raw) + 127) & ~(uintptr_t)127);
    const uint32_t sbase = s2u(sb);

    const int tid = threadIdx.x;
    const int wid = tid >> 5;
    const int lane = tid & 31;
    const int wm = (wid >> 2) * 64;
    const int wn = (wid & 3) * 32;

    const int ntiles = (M / BM) * NTX;
    const int bx = (int)blockIdx.x, gsz = (int)gridDim.x;
    const int myTiles = (ntiles - bx + gsz - 1) / gsz;
    const int G = myTiles * KI;

    auto load_g = [&](int g) {
        const int lt = g / KI;
        const int kk = g % KI;
        const int tile = bx + lt * gsz;
        const int tm0 = (tile / NTX) * BM;
        const int tn0 = (tile % NTX) * BN;
        const int k0 = kk * BK;
        const int s = g % 3;
        uint32_t aB = sbase + s * STG_BYTES;
        uint32_t bB = aB + A_ST;
        const __half* Ap = A + (size_t)tm0 * K + k0;
        const __half* Bp = B + (size_t)tn0 * K + k0;
#pragma unroll
        for (int i = 0; i < 4; i++) {
            int idx = tid + i * 256;
            int row = idx >> 3, c = idx & 7;
            cp16(aB + (uint32_t)(row * ROWB + ((c ^ (row & 7)) << 4)),
                 Ap + (size_t)row * K + c * 8);
        }
#pragma unroll
        for (int i = 0; i < 4; i++) {
            int idx = tid + i * 256;
            int row = idx >> 3, c = idx & 7;
            cp16(bB + (uint32_t)(row * ROWB + ((c ^ (row & 7)) << 4)),
                 Bp + (size_t)row * K + c * 8);
        }
    };

    const int rowA = wm + (lane & 15);
    const uint32_t rbA = (uint32_t)(rowA * ROWB);
    const uint32_t swA = (uint32_t)(rowA & 7);
    const uint32_t hiA = (uint32_t)(lane >> 4);
    const int rowB = wn + ((lane >> 4) << 3) + (lane & 7);
    const uint32_t rbB = (uint32_t)(A_ST + rowB * ROWB);
    const uint32_t swB = (uint32_t)(rowB & 7);
    const uint32_t hiB = (uint32_t)((lane & 8) >> 3);

    float acc[4][4][4];
#pragma unroll
    for (int i = 0; i < 4; i++)
#pragma unroll
        for (int j = 0; j < 4; j++)
#pragma unroll
            for (int e = 0; e < 4; e++) acc[i][j][e] = 0.0f;

    auto do_slice = [&](uint32_t stg, int ks) {
        uint32_t af[4][4], bf[4][2];
        const uint32_t ca = (uint32_t)(2 * ks) + hiA;
        const uint32_t cb = (uint32_t)(2 * ks) + hiB;
#pragma unroll
        for (int i = 0; i < 4; i++)
            ldsm_x4(af[i][0], af[i][1], af[i][2], af[i][3],
                    stg + rbA + (uint32_t)(i * 16 * ROWB) + ((ca ^ swA) << 4));
#pragma unroll
        for (int p = 0; p < 2; p++)
            ldsm_x4(bf[2 * p][0], bf[2 * p][1], bf[2 * p + 1][0], bf[2 * p + 1][1],
                    stg + rbB + (uint32_t)(p * 16 * ROWB) + ((cb ^ swB) << 4));
#pragma unroll
        for (int i = 0; i < 4; i++)
#pragma unroll
            for (int j = 0; j < 4; j++)
                mma16816(acc[i][j], af[i], bf[j]);
    };

    if (G == 0) return;

    load_g(0); cp_commit();
    if (G > 1) load_g(1);
    cp_commit();

    for (int g = 0; g < G; g++) {
        cp_wait<1>();
        __syncthreads();
        const uint32_t stg = sbase + (g % 3) * STG_BYTES;
        do_slice(stg, 0);
        if (g + 2 < G) load_g(g + 2);
        cp_commit();
#pragma unroll
        for (int ks = 1; ks < 4; ks++) do_slice(stg, ks);

        if (((g + 1) % KI) == 0) {
            const int tile = bx + (g / KI) * gsz;
            const int m0 = (tile / NTX) * BM;
            const int n0 = (tile % NTX) * BN;
#pragma unroll
            for (int i = 0; i < 4; i++) {
#pragma unroll
                for (int j = 0; j < 4; j++) {
                    int row = m0 + wm + i * 16 + (lane >> 2);
                    int col = n0 + wn + j * 8 + (lane & 3) * 2;
                    *(float2*)(Out + (size_t)row * Nfull + col) =
                        make_float2(acc[i][j][0], acc[i][j][1]);
                    *(float2*)(Out + (size_t)(row + 8) * Nfull + col) =
                        make_float2(acc[i][j][2], acc[i][j][3]);
#pragma unroll
                    for (int e = 0; e < 4; e++) acc[i][j][e] = 0.0f;
                }
            }
        }
    }
    cp_wait<0>();
}

// ================= host =================
extern "C" void kernel_launch(void* const* d_in, const int* in_sizes, int n_in,
                              void* d_out, int out_size) {
    const float* x          = (const float*)d_in[0];
    const float* up_wq      = (const float*)d_in[1];
    const float* up_scale   = (const float*)d_in[2];
    const float* down_wq    = (const float*)d_in[3];
    const float* down_scale = (const float*)d_in[4];
    const float* up_signs   = (const float*)d_in[5];
    const float* down_signs = (const float*)d_in[6];

    __half *pXS, *pW1, *pW2, *pAR;
    { void* p; cudaGetSymbolAddress(&p, g_XS); pXS = (__half*)p; }
    { void* p; cudaGetSymbolAddress(&p, g_W1); pW1 = (__half*)p; }
    { void* p; cudaGetSymbolAddress(&p, g_W2); pW2 = (__half*)p; }
    { void* p; cudaGetSymbolAddress(&p, g_AR); pAR = (__half*)p; }

    int sms = 148;
    cudaDeviceGetAttribute(&sms, cudaDevAttrMultiProcessorCount, 0);

    cudaFuncSetAttribute(gemm1_mma, cudaFuncAttributeMaxDynamicSharedMemorySize, DYN_SMEM);
    cudaFuncSetAttribute(gemm2_mma<64, 8>, cudaFuncAttributeMaxDynamicSharedMemorySize, DYN_SMEM);

    // 1) merged prep: XS = x*up_signs ; W1' = (W1*H)*up_scale ; W2'' = (W2*H)*signs*down_scale
    prep_kernel<<<XS_BLK + W1_BLK + W2_BLK, 256>>>(x, up_signs, pXS,
                                                   up_wq, up_scale, pW1,
                                                   down_wq, down_signs, down_scale, pW2);

    // 2) GEMM1 (non-persistent): gelu(XS @ W1'^T) -> AR fp16
    {
        dim3 grid(D_MID / BN, T_ROWS / BM);  // (32, 128)
        gemm1_mma<<<grid, 256, DYN_SMEM>>>(pXS, pW1, pAR, T_ROWS, D_MID, D_IN);
    }

    // 3) GEMM2 (persistent): AR @ W2''^T -> fp32 out
    {
        int ntiles = (T_ROWS / BM) * (D_OUT / BN);   // 1024
        int grid = 2 * sms; if (grid > ntiles) grid = ntiles;
        gemm2_mma<64, 8><<<grid, 256, DYN_SMEM>>>(pAR, pW2, (float*)d_out,
                                                  T_ROWS, D_OUT, D_MID);
    }
}

// round 17
// speedup vs baseline: 1.0587x; 1.0340x over previous
#include <cuda_runtime.h>
#include <cuda_fp16.h>
#include <cstdint>

#define T_ROWS 16384
#define D_IN   1024
#define D_MID  4096
#define D_OUT  1024

// GEMM tiling: 128x128 CTA tile, 8 warps (2Mx4N) of 64x32, 2 CTAs/SM
#define BM 128
#define BN 128
#define BK 64
#define ROWB 128                   // bytes per smem row (64 halves), XOR-swizzled
#define A_ST (BM * ROWB)           // 16384 B
#define B_ST (BN * ROWB)           // 16384 B
#define STG_BYTES (A_ST + B_ST)    // 32768 B
#define DYN_SMEM (3 * STG_BYTES + 128)   // 98432 B -> 2 CTAs per SM

// -------- scratch (static device globals; no allocs allowed) --------
__device__ __half g_XS[(size_t)T_ROWS * D_IN];    // x * up_signs, fp16
__device__ __half g_W1[(size_t)D_MID * D_IN];     // (up_wq * H) * up_scale[row], fp16
__device__ __half g_W2[(size_t)D_OUT * D_MID];    // (down_wq*H)*diag(down_signs)*down_scale[row], fp16
__device__ __half g_AR[(size_t)T_ROWS * D_MID];   // gelu(h), fp16

// ---------------- helpers ----------------
static __device__ __forceinline__ uint32_t s2u(const void* p) {
    return (uint32_t)__cvta_generic_to_shared(p);
}
static __device__ __forceinline__ void cp16(uint32_t dst, const void* src) {
    asm volatile("cp.async.cg.shared.global [%0], [%1], 16;" :: "r"(dst), "l"(src));
}
static __device__ __forceinline__ void cp_commit() { asm volatile("cp.async.commit_group;" ::: "memory"); }
template <int N>
static __device__ __forceinline__ void cp_wait() { asm volatile("cp.async.wait_group %0;" :: "n"(N) : "memory"); }

static __device__ __forceinline__ void ldsm_x4(uint32_t& r0, uint32_t& r1, uint32_t& r2, uint32_t& r3,
                                               uint32_t addr) {
    asm volatile("ldmatrix.sync.aligned.m8n8.x4.shared.b16 {%0,%1,%2,%3}, [%4];"
                 : "=r"(r0), "=r"(r1), "=r"(r2), "=r"(r3) : "r"(addr));
}
static __device__ __forceinline__ void mma16816(float* c, const uint32_t* a, const uint32_t* b) {
    asm volatile(
        "mma.sync.aligned.m16n8k16.row.col.f32.f16.f16.f32 "
        "{%0,%1,%2,%3}, {%4,%5,%6,%7}, {%8,%9}, {%0,%1,%2,%3};"
        : "+f"(c[0]), "+f"(c[1]), "+f"(c[2]), "+f"(c[3])
        : "r"(a[0]), "r"(a[1]), "r"(a[2]), "r"(a[3]), "r"(b[0]), "r"(b[1]));
}
// gelu(v) = 0.5*v*(1 + tanh(0.79788456*(v + 0.044715 v^3))) — single MUFU.TANH
static __device__ __forceinline__ float gelu_f(float v) {
    float u = fmaf(0.035677408136300125f * v, v * v, 0.7978845608028654f * v);
    float th;
    asm("tanh.approx.f32 %0, %1;" : "=f"(th) : "f"(u));
    return 0.5f * v * (1.0f + th);
}

// ================= merged prep =================
// blocks [0, XS_BLK): XS = x * up_signs
// blocks [XS_BLK, +W1_BLK): W1' = (W1*H) * up_scale[row]
// blocks [.., +W2_BLK): W2'' = (W2*H) * diag(down_signs) * down_scale[row]
#define XS_BLK (T_ROWS * D_IN / 4 / 256)           // 16384
#define W1_BLK ((D_MID * D_IN / 128) / 8)          // 4096
#define W2_BLK ((D_OUT * D_MID / 128) / 8)         // 4096
__global__ void prep_kernel(const float* __restrict__ x, const float* __restrict__ up_signs,
                            __half* __restrict__ XS,
                            const float* __restrict__ w1, const float* __restrict__ up_scale,
                            __half* __restrict__ W1,
                            const float* __restrict__ w2, const float* __restrict__ down_signs,
                            const float* __restrict__ down_scale, __half* __restrict__ W2) {
    int b = blockIdx.x;
    if (b < XS_BLK) {
        int i = b * 256 + threadIdx.x;
        float4 v = reinterpret_cast<const float4*>(x)[i];
        int col = (i * 4) & (D_IN - 1);
        float4 s = *reinterpret_cast<const float4*>(up_signs + col);
        reinterpret_cast<__half2*>(XS)[2 * i]     = __floats2half2_rn(v.x * s.x, v.y * s.y);
        reinterpret_cast<__half2*>(XS)[2 * i + 1] = __floats2half2_rn(v.z * s.z, v.w * s.w);
        return;
    }
    const float* w;  __half* out;  const float* signs;  const float* rowscale;  int rowlen;
    if (b < XS_BLK + W1_BLK) { b -= XS_BLK;          w = w1; out = W1; signs = nullptr;    rowscale = up_scale;   rowlen = D_IN;  }
    else                     { b -= XS_BLK + W1_BLK; w = w2; out = W2; signs = down_signs; rowscale = down_scale; rowlen = D_MID; }
    int warp = b * 8 + (threadIdx.x >> 5);
    int lane = threadIdx.x & 31;
    size_t base = (size_t)warp * 128;
    int colbase = (int)(base % (size_t)rowlen);
    int wrow = (int)(base / (size_t)rowlen);       // weight row = output column
    float v[4];
#pragma unroll
    for (int j = 0; j < 4; j++) v[j] = w[base + lane + 32 * j];
#pragma unroll
    for (int len = 1; len <= 16; len <<= 1) {
#pragma unroll
        for (int j = 0; j < 4; j++) {
            float o = __shfl_xor_sync(0xffffffffu, v[j], len);
            v[j] = (lane & len) ? (o - v[j]) : (v[j] + o);
        }
    }
    float t0 = v[0] + v[1], t1 = v[0] - v[1], t2 = v[2] + v[3], t3 = v[2] - v[3];
    v[0] = t0 + t2; v[2] = t0 - t2; v[1] = t1 + t3; v[3] = t1 - t3;
    float nrm = 0.08838834764831845f * rowscale[wrow];   // 1/sqrt(128) * per-row scale
    if (signs) {
#pragma unroll
        for (int j = 0; j < 4; j++)
            out[base + lane + 32 * j] = __float2half(v[j] * nrm * signs[colbase + lane + 32 * j]);
    } else {
#pragma unroll
        for (int j = 0; j < 4; j++)
            out[base + lane + 32 * j] = __float2half(v[j] * nrm);
    }
}

// ================= GEMM1: non-persistent =================
// out fp16 = gelu(acc)  (scale pre-folded into W1)
__global__ __launch_bounds__(256, 2)
void gemm1_mma(const __half* __restrict__ A, const __half* __restrict__ B,
               __half* __restrict__ Out, int M, int Nfull, int K) {
    extern __shared__ char dsm_raw[];
    char* sb = (char*)((((uintptr_t)dsm_raw) + 127) & ~(uintptr_t)127);
    const uint32_t sbase = s2u(sb);

    const int tid = threadIdx.x;
    const int wid = tid >> 5;
    const int lane = tid & 31;
    const int wm = (wid >> 2) * 64;
    const int wn = (wid & 3) * 32;
    const int m0 = blockIdx.y * BM;
    const int n0 = blockIdx.x * BN;
    const int KI = K / BK;

    float acc[4][4][4];
#pragma unroll
    for (int i = 0; i < 4; i++)
#pragma unroll
        for (int j = 0; j < 4; j++)
#pragma unroll
            for (int e = 0; e < 4; e++) acc[i][j][e] = 0.0f;

    auto load_stage = [&](int s, int kk) {
        const int k0 = kk * BK;
        uint32_t aB = sbase + s * STG_BYTES;
        uint32_t bB = aB + A_ST;
        const __half* Ap = A + (size_t)m0 * K + k0;
        const __half* Bp = B + (size_t)n0 * K + k0;
#pragma unroll
        for (int i = 0; i < 4; i++) {
            int idx = tid + i * 256;
            int row = idx >> 3, c = idx & 7;
            cp16(aB + (uint32_t)(row * ROWB + ((c ^ (row & 7)) << 4)),
                 Ap + (size_t)row * K + c * 8);
        }
#pragma unroll
        for (int i = 0; i < 4; i++) {
            int idx = tid + i * 256;
            int row = idx >> 3, c = idx & 7;
            cp16(bB + (uint32_t)(row * ROWB + ((c ^ (row & 7)) << 4)),
                 Bp + (size_t)row * K + c * 8);
        }
    };

    const int rowA = wm + (lane & 15);
    const uint32_t rbA = (uint32_t)(rowA * ROWB);
    const uint32_t swA = (uint32_t)(rowA & 7);
    const uint32_t hiA = (uint32_t)(lane >> 4);
    const int rowB = wn + ((lane >> 4) << 3) + (lane & 7);
    const uint32_t rbB = (uint32_t)(A_ST + rowB * ROWB);
    const uint32_t swB = (uint32_t)(rowB & 7);
    const uint32_t hiB = (uint32_t)((lane & 8) >> 3);

    auto do_slice = [&](uint32_t stg, int ks) {
        uint32_t af[4][4], bf[4][2];
        const uint32_t ca = (uint32_t)(2 * ks) + hiA;
        const uint32_t cb = (uint32_t)(2 * ks) + hiB;
#pragma unroll
        for (int i = 0; i < 4; i++)
            ldsm_x4(af[i][0], af[i][1], af[i][2], af[i][3],
                    stg + rbA + (uint32_t)(i * 16 * ROWB) + ((ca ^ swA) << 4));
#pragma unroll
        for (int p = 0; p < 2; p++)
            ldsm_x4(bf[2 * p][0], bf[2 * p][1], bf[2 * p + 1][0], bf[2 * p + 1][1],
                    stg + rbB + (uint32_t)(p * 16 * ROWB) + ((cb ^ swB) << 4));
#pragma unroll
        for (int i = 0; i < 4; i++)
#pragma unroll
            for (int j = 0; j < 4; j++)
                mma16816(acc[i][j], af[i], bf[j]);
    };

    load_stage(0, 0); cp_commit();
    if (KI > 1) load_stage(1, 1);
    cp_commit();

    for (int k = 0; k < KI; k++) {
        cp_wait<1>();
        __syncthreads();
        const uint32_t stg = sbase + (k % 3) * STG_BYTES;
        do_slice(stg, 0);
        if (k + 2 < KI) load_stage((k + 2) % 3, k + 2);
        cp_commit();
#pragma unroll
        for (int ks = 1; ks < 4; ks++) do_slice(stg, ks);
    }
    cp_wait<0>();

#pragma unroll
    for (int i = 0; i < 4; i++) {
#pragma unroll
        for (int j = 0; j < 4; j++) {
            int row = m0 + wm + i * 16 + (lane >> 2);
            int col = n0 + wn + j * 8 + (lane & 3) * 2;
            float v00 = gelu_f(acc[i][j][0]);
            float v01 = gelu_f(acc[i][j][1]);
            float v10 = gelu_f(acc[i][j][2]);
            float v11 = gelu_f(acc[i][j][3]);
            *(__half2*)(Out + (size_t)row * Nfull + col) = __floats2half2_rn(v00, v01);
            *(__half2*)(Out + (size_t)(row + 8) * Nfull + col) = __floats2half2_rn(v10, v11);
        }
    }
}

// ================= GEMM2: persistent continuous pipeline =================
// out fp32 = acc  (scale/signs pre-folded into W2); KI = K/BK, NTX = N/BN compile-time.
template <int KI, int NTX>
__global__ __launch_bounds__(256, 2)
void gemm2_mma(const __half* __restrict__ A, const __half* __restrict__ B,
               float* __restrict__ Out, int M, int Nfull, int K) {
    extern __shared__ char dsm_raw[];
    char* sb = (char*)((((uintptr_t)dsm_raw) + 127) & ~(uintptr_t)127);
    const uint32_t sbase = s2u(sb);

    const int tid = threadIdx.x;
    const int wid = tid >> 5;
    const int lane = tid & 31;
    const int wm = (wid >> 2) * 64;
    const int wn = (wid & 3) * 32;

    const int ntiles = (M / BM) * NTX;
    const int bx = (int)blockIdx.x, gsz = (int)gridDim.x;
    const int myTiles = (ntiles - bx + gsz - 1) / gsz;
    const int G = myTiles * KI;

    auto load_g = [&](int g) {
        const int lt = g / KI;
        const int kk = g % KI;
        const int tile = bx + lt * gsz;
        const int tm0 = (tile / NTX) * BM;
        const int tn0 = (tile % NTX) * BN;
        const int k0 = kk * BK;
        const int s = g % 3;
        uint32_t aB = sbase + s * STG_BYTES;
        uint32_t bB = aB + A_ST;
        const __half* Ap = A + (size_t)tm0 * K + k0;
        const __half* Bp = B + (size_t)tn0 * K + k0;
#pragma unroll
        for (int i = 0; i < 4; i++) {
            int idx = tid + i * 256;
            int row = idx >> 3, c = idx & 7;
            cp16(aB + (uint32_t)(row * ROWB + ((c ^ (row & 7)) << 4)),
                 Ap + (size_t)row * K + c * 8);
        }
#pragma unroll
        for (int i = 0; i < 4; i++) {
            int idx = tid + i * 256;
            int row = idx >> 3, c = idx & 7;
            cp16(bB + (uint32_t)(row * ROWB + ((c ^ (row & 7)) << 4)),
                 Bp + (size_t)row * K + c * 8);
        }
    };

    const int rowA = wm + (lane & 15);
    const uint32_t rbA = (uint32_t)(rowA * ROWB);
    const uint32_t swA = (uint32_t)(rowA & 7);
    const uint32_t hiA = (uint32_t)(lane >> 4);
    const int rowB = wn + ((lane >> 4) << 3) + (lane & 7);
    const uint32_t rbB = (uint32_t)(A_ST + rowB * ROWB);
    const uint32_t swB = (uint32_t)(rowB & 7);
    const uint32_t hiB = (uint32_t)((lane & 8) >> 3);

    float acc[4][4][4];
#pragma unroll
    for (int i = 0; i < 4; i++)
#pragma unroll
        for (int j = 0; j < 4; j++)
#pragma unroll
            for (int e = 0; e < 4; e++) acc[i][j][e] = 0.0f;

    auto do_slice = [&](uint32_t stg, int ks) {
        uint32_t af[4][4], bf[4][2];
        const uint32_t ca = (uint32_t)(2 * ks) + hiA;
        const uint32_t cb = (uint32_t)(2 * ks) + hiB;
#pragma unroll
        for (int i = 0; i < 4; i++)
            ldsm_x4(af[i][0], af[i][1], af[i][2], af[i][3],
                    stg + rbA + (uint32_t)(i * 16 * ROWB) + ((ca ^ swA) << 4));
#pragma unroll
        for (int p = 0; p < 2; p++)
            ldsm_x4(bf[2 * p][0], bf[2 * p][1], bf[2 * p + 1][0], bf[2 * p + 1][1],
                    stg + rbB + (uint32_t)(p * 16 * ROWB) + ((cb ^ swB) << 4));
#pragma unroll
        for (int i = 0; i < 4; i++)
#pragma unroll
            for (int j = 0; j < 4; j++)
                mma16816(acc[i][j], af[i], bf[j]);
    };

    if (G == 0) return;

    load_g(0); cp_commit();
    if (G > 1) load_g(1);
    cp_commit();

    for (int g = 0; g < G; g++) {
        cp_wait<1>();
        __syncthreads();
        const uint32_t stg = sbase + (g % 3) * STG_BYTES;
        do_slice(stg, 0);
        if (g + 2 < G) load_g(g + 2);
        cp_commit();
#pragma unroll
        for (int ks = 1; ks < 4; ks++) do_slice(stg, ks);

        if (((g + 1) % KI) == 0) {
            const int tile = bx + (g / KI) * gsz;
            const int m0 = (tile / NTX) * BM;
            const int n0 = (tile % NTX) * BN;
#pragma unroll
            for (int i = 0; i < 4; i++) {
#pragma unroll
                for (int j = 0; j < 4; j++) {
                    int row = m0 + wm + i * 16 + (lane >> 2);
                    int col = n0 + wn + j * 8 + (lane & 3) * 2;
                    *(float2*)(Out + (size_t)row * Nfull + col) =
                        make_float2(acc[i][j][0], acc[i][j][1]);
                    *(float2*)(Out + (size_t)(row + 8) * Nfull + col) =
                        make_float2(acc[i][j][2], acc[i][j][3]);
#pragma unroll
                    for (int e = 0; e < 4; e++) acc[i][j][e] = 0.0f;
                }
            }
        }
    }
    cp_wait<0>();
}

// ================= host =================
extern "C" void kernel_launch(void* const* d_in, const int* in_sizes, int n_in,
                              void* d_out, int out_size) {
    const float* x          = (const float*)d_in[0];
    const float* up_wq      = (const float*)d_in[1];
    const float* up_scale   = (const float*)d_in[2];
    const float* down_wq    = (const float*)d_in[3];
    const float* down_scale = (const float*)d_in[4];
    const float* up_signs   = (const float*)d_in[5];
    const float* down_signs = (const float*)d_in[6];

    __half *pXS, *pW1, *pW2, *pAR;
    { void* p; cudaGetSymbolAddress(&p, g_XS); pXS = (__half*)p; }
    { void* p; cudaGetSymbolAddress(&p, g_W1); pW1 = (__half*)p; }
    { void* p; cudaGetSymbolAddress(&p, g_W2); pW2 = (__half*)p; }
    { void* p; cudaGetSymbolAddress(&p, g_AR); pAR = (__half*)p; }

    int sms = 148;
    cudaDeviceGetAttribute(&sms, cudaDevAttrMultiProcessorCount, 0);

    cudaFuncSetAttribute(gemm1_mma, cudaFuncAttributeMaxDynamicSharedMemorySize, DYN_SMEM);
    cudaFuncSetAttribute(gemm2_mma<64, 8>, cudaFuncAttributeMaxDynamicSharedMemorySize, DYN_SMEM);

    // 1) merged prep: XS = x*up_signs ; W1' = (W1*H)*up_scale ; W2'' = (W2*H)*signs*down_scale
    prep_kernel<<<XS_BLK + W1_BLK + W2_BLK, 256>>>(x, up_signs, pXS,
                                                   up_wq, up_scale, pW1,
                                                   down_wq, down_signs, down_scale, pW2);

    // 2) GEMM1 (non-persistent): gelu(XS @ W1'^T) -> AR fp16
    {
        dim3 grid(D_MID / BN, T_ROWS / BM);  // (32, 128)
        gemm1_mma<<<grid, 256, DYN_SMEM>>>(pXS, pW1, pAR, T_ROWS, D_MID, D_IN);
    }

    // 3) GEMM2 (persistent): AR @ W2''^T -> fp32 out
    {
        int ntiles = (T_ROWS / BM) * (D_OUT / BN);   // 1024
        int grid = 2 * sms; if (grid > ntiles) grid = ntiles;
        gemm2_mma<64, 8><<<grid, 256, DYN_SMEM>>>(pAR, pW2, (float*)d_out,
                                                  T_ROWS, D_OUT, D_MID);
    }
}